// round 1
// baseline (speedup 1.0000x reference)
#include <cuda_runtime.h>

#define NB 16
#define DD 128
#define NN 16
#define EE 120

// Scratch (allocation-free rule: __device__ globals)
__device__ float g_T[2 * NB * DD * NN];   // [mat][b][k][v]  lsym @ F_tgt
__device__ float g_P[2 * NB * NN * NN];   // [mat][b][u][v]  F_src^T lsym F_tgt
__device__ float g_Mp[NB * NN * NN];      // [b][u][v]       U_src^T U_tgt
__device__ float g_mb[NB * EE];           // combined src*tgt edge mask

// strict-upper-triangle edge index (numpy triu_indices(16, k=1) row-major order)
__device__ __forceinline__ int eidx(int i, int j) {
    return i * 15 - ((i * (i - 1)) >> 1) + (j - i - 1);
}

// K1: T[mat][b][k][v] = sum_j relu(lam[k][j] + lam[j][k]) * F_tgt[b][j][v]
// grid 256 = mat(2) x b(16) x kslice(8), 128 threads
__global__ void k1(const float* __restrict__ lam1, const float* __restrict__ lam2,
                   const float* __restrict__ F_tgt) {
    int blk = blockIdx.x;
    int mat = blk >> 7;
    int b   = (blk >> 3) & 15;
    int ks  = blk & 7;
    const float* lam = mat ? lam2 : lam1;

    __shared__ float sF[DD * NN];
    const float* Fb = F_tgt + b * DD * NN;
    for (int i = threadIdx.x; i < DD * NN; i += 128) sF[i] = Fb[i];
    __syncthreads();

    int t  = threadIdx.x;
    int kl = t >> 3;          // 0..15
    int v0 = t & 7;           // 0..7  (handles v0 and v0+8)
    int k  = ks * 16 + kl;

    const float* lrow = lam + k * DD;
    float a0 = 0.f, a1 = 0.f;
#pragma unroll 8
    for (int j = 0; j < DD; ++j) {
        float ls = fmaxf(lrow[j] + lam[j * DD + k], 0.f);
        a0 = fmaf(ls, sF[j * NN + v0],     a0);
        a1 = fmaf(ls, sF[j * NN + v0 + 8], a1);
    }
    float* T = g_T + ((mat * NB + b) * DD + k) * NN;
    T[v0]     = a0;
    T[v0 + 8] = a1;
}

// K2: P[mat][b][u][v] = sum_k F_src[b][k][u] * T[mat][b][k][v]
// Also (mat==0 blocks): mb and Mp.  grid (16, 2), 256 threads
__global__ void k2(const float* __restrict__ F_src,
                   const float* __restrict__ U_src, const float* __restrict__ U_tgt,
                   const int* __restrict__ A_src, const int* __restrict__ A_tgt) {
    int b = blockIdx.x, mat = blockIdx.y;

    __shared__ float sFs[DD * NN];
    __shared__ float sT[DD * NN];
    const float* Fb = F_src + b * DD * NN;
    const float* Tb = g_T + (mat * NB + b) * DD * NN;
    for (int i = threadIdx.x; i < DD * NN; i += 256) {
        sFs[i] = Fb[i];
        sT[i]  = Tb[i];
    }
    __syncthreads();

    int t = threadIdx.x;
    int u = t >> 4, v = t & 15;
    float a = 0.f;
#pragma unroll 8
    for (int k = 0; k < DD; ++k)
        a = fmaf(sFs[k * NN + u], sT[k * NN + v], a);
    g_P[(mat * NB + b) * 256 + t] = a;

    if (mat == 0) {
        if (t < EE)
            g_mb[b * EE + t] =
                (A_src[b * EE + t] > 0 && A_tgt[b * EE + t] > 0) ? 1.f : 0.f;
        // Mp[u][v] = sum_d U_src[b][d][u] * U_tgt[b][d][v]
        const float* Us = U_src + b * NN * NN;
        const float* Ut = U_tgt + b * NN * NN;
        float s = 0.f;
#pragma unroll
        for (int d = 0; d < NN; ++d)
            s = fmaf(Us[d * NN + u], Ut[d * NN + v], s);
        g_Mp[b * 256 + t] = s;
    }
}

// K3: out[b, i2*16+i1, j2*16+j1] = edge term + diag term
// grid (16 b, 16 i2), 256 threads: thread = (i1 = t>>4, j2 = t&15), 16 j1 each
__global__ void k3(float* __restrict__ out) {
    int b = blockIdx.x, i2 = blockIdx.y;
    __shared__ float sP1[256], sP2[256], smb[EE], sMp[16];
    int t = threadIdx.x;
    sP1[t] = g_P[b * 256 + t];
    sP2[t] = g_P[(NB + b) * 256 + t];
    if (t < EE) smb[t] = g_mb[b * EE + t];
    if (t < 16) sMp[t] = g_Mp[b * 256 + i2 * 16 + t];
    __syncthreads();

    int i1 = t >> 4, j2 = t & 15;

    float me2 = 0.f;
    if (i2 < j2) me2 = smb[eidx(i2, j2)];
    float p1a = sP1[i2 * 16 + i1];   // P1[i2][i1]
    float p2b = sP2[j2 * 16 + i1];   // P2[j2][i1]

    float vals[16];
#pragma unroll
    for (int j1 = 0; j1 < 16; ++j1) {
        float val = 0.f;
        if (i2 < j2 && i1 < j1) {
            float me1 = smb[eidx(i1, j1)];
            val = me2 * me1 *
                  (p1a + sP2[i2 * 16 + j1] + p2b + sP1[j2 * 16 + j1]);
        }
        if (i2 == j2 && j1 == i1)   // diagonal of diag(Mp.flatten())
            val += sMp[i1];
        vals[j1] = val;
    }

    // row p = i2*16+i1, cols j2*16 .. j2*16+15 : 64B contiguous per thread
    float4* o = reinterpret_cast<float4*>(
        out + ((size_t)b * 65536u) + (i2 * 16 + i1) * 256 + j2 * 16);
#pragma unroll
    for (int q = 0; q < 4; ++q)
        o[q] = make_float4(vals[4 * q], vals[4 * q + 1],
                           vals[4 * q + 2], vals[4 * q + 3]);
}

extern "C" void kernel_launch(void* const* d_in, const int* in_sizes, int n_in,
                              void* d_out, int out_size) {
    const int*   A_src = (const int*)d_in[0];
    const int*   A_tgt = (const int*)d_in[1];
    const float* F_src = (const float*)d_in[2];
    const float* F_tgt = (const float*)d_in[3];
    const float* U_src = (const float*)d_in[4];
    const float* U_tgt = (const float*)d_in[5];
    const float* lam1  = (const float*)d_in[6];
    const float* lam2  = (const float*)d_in[7];
    float* out = (float*)d_out;

    k1<<<256, 128>>>(lam1, lam2, F_tgt);
    k2<<<dim3(16, 2), 256>>>(F_src, U_src, U_tgt, A_src, A_tgt);
    k3<<<dim3(16, 16), 256>>>(out);
}

// round 2
// speedup vs baseline: 1.3252x; 1.3252x over previous
#include <cuda_runtime.h>

#define NB 16
#define DD 128
#define NN 16
#define EE 120

// Scratch (allocation-free rule: __device__ globals)
__device__ float g_T[2 * NB * DD * NN];   // [mat][b][k][v]  lsym @ F_tgt
__device__ float g_P[2 * NB * NN * NN];   // [mat][b][u][v]  F_src^T lsym F_tgt
__device__ float g_Mp[NB * NN * NN];      // [b][u][v]       U_src^T U_tgt
__device__ float g_mb[NB * EE];           // combined src*tgt edge mask

// strict-upper-triangle edge index (numpy triu_indices(16, k=1) row-major order)
__device__ __forceinline__ int eidx(int i, int j) {
    return i * 15 - ((i * (i - 1)) >> 1) + (j - i - 1);
}

#define WPAD 132   // 128 + 4 pad: kl*132 % 32 = kl*4 -> distinct banks per kl

// K1: T[mat][b][k][v] = sum_j relu(lam[k][j] + lam[j][k]) * F_tgt[b][j][v]
// grid 256 = mat(2) x b(16) x kslice(8), 128 threads.
// lsym slice is staged/built in smem ONCE (float4 transposed load), so the
// serial reduction loop touches only shared memory.
__global__ void k1(const float* __restrict__ lam1, const float* __restrict__ lam2,
                   const float* __restrict__ F_tgt) {
    int blk = blockIdx.x;
    int mat = blk >> 7;
    int b   = (blk >> 3) & 15;
    int ks  = blk & 7;
    int k0  = ks * 16;
    const float* lam = mat ? lam2 : lam1;

    __shared__ float sF[DD * NN];       // F_tgt[b], [j][v]
    __shared__ float sW[16 * WPAD];     // lsym slice, [kl][j] padded

    int t = threadIdx.x;

    // stage F_tgt[b] (8KB, float4 coalesced)
    {
        const float4* F4 = reinterpret_cast<const float4*>(F_tgt + b * DD * NN);
        float4* s4 = reinterpret_cast<float4*>(sF);
        for (int i = t; i < DD * NN / 4; i += 128) s4[i] = F4[i];
    }

    // pass 1: transposed lam slice lam[j][k0+kl] -> sW[kl][j], float4 over kl
    {
        int c = (t & 3) * 4;        // kl base 0,4,8,12
        int jb = t >> 2;            // 0..31
#pragma unroll
        for (int p = 0; p < 4; ++p) {
            int j = jb + 32 * p;
            float4 v = *reinterpret_cast<const float4*>(lam + j * DD + k0 + c);
            sW[(c + 0) * WPAD + j] = v.x;
            sW[(c + 1) * WPAD + j] = v.y;
            sW[(c + 2) * WPAD + j] = v.z;
            sW[(c + 3) * WPAD + j] = v.w;
        }
    }
    __syncthreads();

    // pass 2: add row part (coalesced) + relu, in place
    for (int idx = t; idx < 16 * DD; idx += 128) {
        int kl = idx >> 7, j = idx & 127;
        float w = sW[kl * WPAD + j] + lam[(k0 + kl) * DD + j];
        sW[kl * WPAD + j] = fmaxf(w, 0.f);
    }
    __syncthreads();

    // GEMM slice: thread (kl = t>>3, v0 = t&7) does v0 and v0+8
    int kl = t >> 3;
    int v0 = t & 7;
    const float* wrow = sW + kl * WPAD;
    float a0 = 0.f, a1 = 0.f;
#pragma unroll 16
    for (int j = 0; j < DD; ++j) {
        float w = wrow[j];
        a0 = fmaf(w, sF[j * NN + v0],     a0);
        a1 = fmaf(w, sF[j * NN + v0 + 8], a1);
    }
    float* T = g_T + ((mat * NB + b) * DD + k0 + kl) * NN;
    T[v0]     = a0;
    T[v0 + 8] = a1;
}

// K2: P[mat][b][u][v] = sum_k F_src[b][k][u] * T[mat][b][k][v]
// Also (mat==0 blocks): mb and Mp.  grid (16, 2), 256 threads
__global__ void k2(const float* __restrict__ F_src,
                   const float* __restrict__ U_src, const float* __restrict__ U_tgt,
                   const int* __restrict__ A_src, const int* __restrict__ A_tgt) {
    int b = blockIdx.x, mat = blockIdx.y;

    __shared__ float sFs[DD * NN];
    __shared__ float sT[DD * NN];
    const float4* Fb = reinterpret_cast<const float4*>(F_src + b * DD * NN);
    const float4* Tb = reinterpret_cast<const float4*>(g_T + (mat * NB + b) * DD * NN);
    float4* sFs4 = reinterpret_cast<float4*>(sFs);
    float4* sT4  = reinterpret_cast<float4*>(sT);
    for (int i = threadIdx.x; i < DD * NN / 4; i += 256) {
        sFs4[i] = Fb[i];
        sT4[i]  = Tb[i];
    }
    __syncthreads();

    int t = threadIdx.x;
    int u = t >> 4, v = t & 15;
    float a = 0.f;
#pragma unroll 16
    for (int k = 0; k < DD; ++k)
        a = fmaf(sFs[k * NN + u], sT[k * NN + v], a);
    g_P[(mat * NB + b) * 256 + t] = a;

    if (mat == 0) {
        if (t < EE)
            g_mb[b * EE + t] =
                (A_src[b * EE + t] > 0 && A_tgt[b * EE + t] > 0) ? 1.f : 0.f;
        // Mp[u][v] = sum_d U_src[b][d][u] * U_tgt[b][d][v]
        const float* Us = U_src + b * NN * NN;
        const float* Ut = U_tgt + b * NN * NN;
        float s = 0.f;
#pragma unroll
        for (int d = 0; d < NN; ++d)
            s = fmaf(Us[d * NN + u], Ut[d * NN + v], s);
        g_Mp[b * 256 + t] = s;
    }
}

// K3: out[b, i2*16+i1, j2*16+j1] = edge term + diag term
// grid (16 b, 16 i2), 256 threads: thread = (i1 = t>>4, j2 = t&15), 16 j1 each
__global__ void k3(float* __restrict__ out) {
    int b = blockIdx.x, i2 = blockIdx.y;
    __shared__ float sP1[256], sP2[256], smb[EE], sMp[16];
    int t = threadIdx.x;
    sP1[t] = g_P[b * 256 + t];
    sP2[t] = g_P[(NB + b) * 256 + t];
    if (t < EE) smb[t] = g_mb[b * EE + t];
    if (t < 16) sMp[t] = g_Mp[b * 256 + i2 * 16 + t];
    __syncthreads();

    int i1 = t >> 4, j2 = t & 15;

    float me2 = 0.f;
    if (i2 < j2) me2 = smb[eidx(i2, j2)];
    float p1a = sP1[i2 * 16 + i1];   // P1[i2][i1]
    float p2b = sP2[j2 * 16 + i1];   // P2[j2][i1]

    float vals[16];
#pragma unroll
    for (int j1 = 0; j1 < 16; ++j1) {
        float val = 0.f;
        if (i2 < j2 && i1 < j1) {
            float me1 = smb[eidx(i1, j1)];
            val = me2 * me1 *
                  (p1a + sP2[i2 * 16 + j1] + p2b + sP1[j2 * 16 + j1]);
        }
        if (i2 == j2 && j1 == i1)   // diagonal of diag(Mp.flatten())
            val += sMp[i1];
        vals[j1] = val;
    }

    // row p = i2*16+i1, cols j2*16 .. j2*16+15 : 64B contiguous per thread
    float4* o = reinterpret_cast<float4*>(
        out + ((size_t)b * 65536u) + (i2 * 16 + i1) * 256 + j2 * 16);
#pragma unroll
    for (int q = 0; q < 4; ++q)
        o[q] = make_float4(vals[4 * q], vals[4 * q + 1],
                           vals[4 * q + 2], vals[4 * q + 3]);
}

extern "C" void kernel_launch(void* const* d_in, const int* in_sizes, int n_in,
                              void* d_out, int out_size) {
    const int*   A_src = (const int*)d_in[0];
    const int*   A_tgt = (const int*)d_in[1];
    const float* F_src = (const float*)d_in[2];
    const float* F_tgt = (const float*)d_in[3];
    const float* U_src = (const float*)d_in[4];
    const float* U_tgt = (const float*)d_in[5];
    const float* lam1  = (const float*)d_in[6];
    const float* lam2  = (const float*)d_in[7];
    float* out = (float*)d_out;

    k1<<<256, 128>>>(lam1, lam2, F_tgt);
    k2<<<dim3(16, 2), 256>>>(F_src, U_src, U_tgt, A_src, A_tgt);
    k3<<<dim3(16, 16), 256>>>(out);
}